// round 16
// baseline (speedup 1.0000x reference)
#include <cuda_runtime.h>
#include <cuda_bf16.h>
#include <cstddef>
#include <cstdint>

#define NN_   4000
#define TT_   64
#define FF_   128
#define HH_   128
#define TH_   384
#define KK_   32
#define EE_   64
#define NCH_  8
#define CHN_  (NN_ / NCH_)   // 500

// ---------------- scratch (static device globals; no allocation) --------------
__device__ float g_xg [(size_t)NN_ * TT_ * TH_];
__device__ float g_h1 [(size_t)NN_ * TT_ * HH_];
__device__ float g_es [NN_ * HH_];
__device__ float g_t1 [NN_ * HH_];
__device__ float g_ep [NN_ * HH_];
__device__ float g_er [NN_ * HH_];
__device__ float g_eh [NN_ * HH_];
__device__ float g_eres[NN_ * HH_];
__device__ float g_ea [NN_ * HH_];
__device__ float g_beta[NN_ * KK_];
__device__ float g_m1 [EE_ * HH_];
__device__ float g_m2 [KK_ * HH_];
__device__ float g_m1p[EE_ * NCH_ * HH_];
__device__ float g_m2p[KK_ * NCH_ * HH_];
__device__ float g_idn [NN_];
__device__ float g_ide [EE_];
__device__ float g_isdn[NN_];
__device__ float g_ide2[KK_];

// ---------------- helpers ----------------
__device__ __forceinline__ float sigf(float x) {
    return __fdividef(1.f, 1.f + __expf(-x));
}
__device__ __forceinline__ float tanh_ex(float x) {
    return __fdividef(2.f, 1.f + __expf(-2.f * x)) - 1.f;
}
__device__ __forceinline__ uint32_t smem_u32(const void* p) {
    uint32_t a;
    asm("{ .reg .u64 t; cvta.to.shared.u64 t, %1; cvt.u32.u64 %0, t; }" : "=r"(a) : "l"(p));
    return a;
}
__device__ __forceinline__ uint32_t pack_bf16(float a, float b) {
    __nv_bfloat162 t = __floats2bfloat162_rn(a, b);
    return *(uint32_t*)&t;
}
__device__ __forceinline__ float bf16_rt(float v) {
    return __bfloat162float(__float2bfloat16_rn(v));
}
__device__ __forceinline__ void ldsm_x4(uint32_t* r, uint32_t addr) {
    asm volatile("ldmatrix.sync.aligned.m8n8.x4.shared.b16 {%0,%1,%2,%3}, [%4];"
                 : "=r"(r[0]), "=r"(r[1]), "=r"(r[2]), "=r"(r[3]) : "r"(addr));
}
__device__ __forceinline__ void ldsm_x2(uint32_t* r, uint32_t addr) {
    asm volatile("ldmatrix.sync.aligned.m8n8.x2.shared.b16 {%0,%1}, [%2];"
                 : "=r"(r[0]), "=r"(r[1]) : "r"(addr));
}
__device__ __forceinline__ void mma_bf16(float* d, const uint32_t* a,
                                         uint32_t b0, uint32_t b1) {
    asm volatile(
        "mma.sync.aligned.m16n8k16.row.col.f32.bf16.bf16.f32 "
        "{%0,%1,%2,%3}, {%4,%5,%6,%7}, {%8,%9}, {%0,%1,%2,%3};"
        : "+f"(d[0]), "+f"(d[1]), "+f"(d[2]), "+f"(d[3])
        : "r"(a[0]), "r"(a[1]), "r"(a[2]), "r"(a[3]), "r"(b0), "r"(b1));
}

// ============ mma.sync big GEMM v2: C[M,384] = A[M,128] @ W[384,128]^T + bias =
#define LDPAD 136
#define MMA_SMEM (4 * 128 * LDPAD * 2)

__global__ void __launch_bounds__(256) gemm_mma(const float* __restrict__ A,
                                                const float* __restrict__ W,
                                                const float* __restrict__ bias,
                                                float* __restrict__ C,
                                                int do_ln,
                                                const float* __restrict__ ln_g,
                                                const float* __restrict__ ln_b) {
    extern __shared__ char smem[];
    __nv_bfloat16* As1 = (__nv_bfloat16*)smem;        // [128][LDPAD]
    __nv_bfloat16* As2 = As1 + 128 * LDPAD;
    __nv_bfloat16* Ws1 = As2 + 128 * LDPAD;
    __nv_bfloat16* Ws2 = Ws1 + 128 * LDPAD;
    int tid = threadIdx.x;
    int lane = tid & 31;
    int mBase = blockIdx.x * 128;

    float4 gv = make_float4(1.f, 1.f, 1.f, 1.f), bv4 = make_float4(0.f, 0.f, 0.f, 0.f);
    if (do_ln) {
        gv  = *(const float4*)&ln_g[lane * 4];
        bv4 = *(const float4*)&ln_b[lane * 4];
    }

    #pragma unroll 2
    for (int i = 0; i < 16; ++i) {
        int lin = tid + i * 256;
        int row = lin >> 5, c4 = (lin & 31) * 4;
        float4 v = *(const float4*)&A[(size_t)(mBase + row) * 128 + c4];
        if (do_ln) {
            float s  = v.x + v.y + v.z + v.w;
            float ss = v.x * v.x + v.y * v.y + v.z * v.z + v.w * v.w;
            #pragma unroll
            for (int o = 16; o > 0; o >>= 1) {
                s  += __shfl_xor_sync(0xffffffffu, s,  o);
                ss += __shfl_xor_sync(0xffffffffu, ss, o);
            }
            float mean = s * (1.f / 128.f);
            float var  = ss * (1.f / 128.f) - mean * mean;
            float rstd = rsqrtf(var + 1e-5f);
            v.x = (v.x - mean) * rstd * gv.x + bv4.x;
            v.y = (v.y - mean) * rstd * gv.y + bv4.y;
            v.z = (v.z - mean) * rstd * gv.z + bv4.z;
            v.w = (v.w - mean) * rstd * gv.w + bv4.w;
        }
        uint2 hi = make_uint2(pack_bf16(v.x, v.y), pack_bf16(v.z, v.w));
        uint2 lo = make_uint2(pack_bf16(v.x - bf16_rt(v.x), v.y - bf16_rt(v.y)),
                              pack_bf16(v.z - bf16_rt(v.z), v.w - bf16_rt(v.w)));
        *(uint2*)&As1[row * LDPAD + c4] = hi;
        *(uint2*)&As2[row * LDPAD + c4] = lo;
    }

    int wid = tid >> 5, l = lane;
    int wm = wid >> 2, wn = wid & 3;
    int lrow = (l & 7) + ((l >> 3) & 1) * 8;
    int lk8  = (l >> 4) * 8;
    int trow = l >> 2, tcol = (l & 3) * 2;

    uint32_t aB1 = smem_u32(As1), aB2 = smem_u32(As2);
    uint32_t wB1 = smem_u32(Ws1), wB2 = smem_u32(Ws2);

    for (int nc = 0; nc < 3; ++nc) {
        if (nc > 0) __syncthreads();
        #pragma unroll 2
        for (int i = 0; i < 16; ++i) {
            int lin = tid + i * 256;
            int row = lin >> 5, c4 = (lin & 31) * 4;
            float4 w = *(const float4*)&W[(size_t)(nc * 128 + row) * 128 + c4];
            *(uint2*)&Ws1[row * LDPAD + c4] =
                make_uint2(pack_bf16(w.x, w.y), pack_bf16(w.z, w.w));
            *(uint2*)&Ws2[row * LDPAD + c4] =
                make_uint2(pack_bf16(w.x - bf16_rt(w.x), w.y - bf16_rt(w.y)),
                           pack_bf16(w.z - bf16_rt(w.z), w.w - bf16_rt(w.w)));
        }
        __syncthreads();

        float acc[4][4][4];
        #pragma unroll
        for (int mi = 0; mi < 4; ++mi)
            #pragma unroll
            for (int ni = 0; ni < 4; ++ni)
                #pragma unroll
                for (int q = 0; q < 4; ++q) acc[mi][ni][q] = 0.f;

        uint32_t apass[3] = {aB1, aB2, aB1};
        uint32_t wpass[3] = {wB1, wB1, wB2};
        #pragma unroll
        for (int pass = 0; pass < 3; ++pass) {
            uint32_t ab = apass[pass], bb = wpass[pass];
            #pragma unroll
            for (int ks = 0; ks < 8; ++ks) {
                int k0 = ks * 16;
                uint32_t a[4][4], b[2][4];
                #pragma unroll
                for (int mi = 0; mi < 4; ++mi) {
                    int row = wm * 64 + mi * 16 + lrow;
                    ldsm_x4(a[mi], ab + (uint32_t)(row * LDPAD + k0 + lk8) * 2);
                }
                #pragma unroll
                for (int p = 0; p < 2; ++p) {
                    int nr = wn * 32 + p * 16 + lrow;
                    ldsm_x4(b[p], bb + (uint32_t)(nr * LDPAD + k0 + lk8) * 2);
                }
                #pragma unroll
                for (int mi = 0; mi < 4; ++mi)
                    #pragma unroll
                    for (int ni = 0; ni < 4; ++ni) {
                        int p = ni >> 1, hi = ni & 1;
                        mma_bf16(acc[mi][ni], a[mi], b[p][hi], b[p][hi + 2]);
                    }
            }
        }

        int nBase = nc * 128;
        float bvx[4], bvy[4];
        #pragma unroll
        for (int ni = 0; ni < 4; ++ni) {
            int col = nBase + wn * 32 + ni * 8 + tcol;
            bvx[ni] = bias[col];
            bvy[ni] = bias[col + 1];
        }
        #pragma unroll
        for (int mi = 0; mi < 4; ++mi) {
            size_t row0 = (size_t)mBase + wm * 64 + mi * 16 + trow;
            #pragma unroll
            for (int ni = 0; ni < 4; ++ni) {
                int col = nBase + wn * 32 + ni * 8 + tcol;
                *(float2*)&C[row0 * TH_ + col] =
                    make_float2(acc[mi][ni][0] + bvx[ni], acc[mi][ni][1] + bvy[ni]);
                *(float2*)&C[(row0 + 8) * TH_ + col] =
                    make_float2(acc[mi][ni][2] + bvx[ni], acc[mi][ni][3] + bvy[ni]);
            }
        }
    }
}

// ========== mma.sync GRU scan (tanh_ex for MUFU reduction) ====================
#define WLD 136
#define SCAN2_SMEM ((384 * WLD * 2 + 32 * WLD * 2) * 2)   // 226304 bytes

__global__ void __launch_bounds__(256) gru_scan_mma(const float* __restrict__ xg,
                                                    const float* __restrict__ Whh,
                                                    const float* __restrict__ bhh,
                                                    float* __restrict__ hseq,
                                                    float* __restrict__ hlast) {
    extern __shared__ char smraw[];
    __nv_bfloat16* Whi = (__nv_bfloat16*)smraw;    // [384][WLD]
    __nv_bfloat16* Wlo = Whi + 384 * WLD;
    __nv_bfloat16* Hhi = Wlo + 384 * WLD;          // [32][WLD]
    __nv_bfloat16* Hlo = Hhi + 32 * WLD;
    int tid = threadIdx.x;

    #pragma unroll 4
    for (int i = 0; i < 48; ++i) {
        int lin = tid + i * 256;
        int row = lin >> 5, c4 = (lin & 31) * 4;
        float4 v = *(const float4*)&Whh[row * 128 + c4];
        *(uint2*)&Whi[row * WLD + c4] = make_uint2(pack_bf16(v.x, v.y), pack_bf16(v.z, v.w));
        *(uint2*)&Wlo[row * WLD + c4] =
            make_uint2(pack_bf16(v.x - bf16_rt(v.x), v.y - bf16_rt(v.y)),
                       pack_bf16(v.z - bf16_rt(v.z), v.w - bf16_rt(v.w)));
    }
    for (int i = tid; i < 32 * WLD / 2; i += 256) {
        ((uint32_t*)Hhi)[i] = 0u;
        ((uint32_t*)Hlo)[i] = 0u;
    }

    int w = tid >> 5, l = tid & 31;
    int trow = l >> 2, tcol = (l & 3) * 2;
    int lrow = (l & 7) + ((l >> 3) & 1) * 8;
    int lk8  = (l >> 4) * 8;
    int lb   = l & 15;
    int n0 = blockIdx.x * 32;
    uint32_t hiB = smem_u32(Hhi), loB = smem_u32(Hlo);
    uint32_t whiB = smem_u32(Whi), wloB = smem_u32(Wlo);

    float bias[6][2];
    #pragma unroll
    for (int ii = 0; ii < 6; ++ii) {
        bias[ii][0] = bhh[w * 8 + ii * 64 + tcol];
        bias[ii][1] = bhh[w * 8 + ii * 64 + tcol + 1];
    }
    float hp[2][2][2][2];
    #pragma unroll
    for (int mi = 0; mi < 2; ++mi)
        #pragma unroll
        for (int ii = 0; ii < 2; ++ii)
            #pragma unroll
            for (int rh = 0; rh < 2; ++rh) {
                hp[mi][ii][rh][0] = 0.f;
                hp[mi][ii][rh][1] = 0.f;
            }
    __syncthreads();

    for (int t = 0; t < TT_; ++t) {
        float2 xv[2][6][2];
        #pragma unroll
        for (int mi = 0; mi < 2; ++mi)
            #pragma unroll
            for (int rh = 0; rh < 2; ++rh) {
                int rl = mi * 16 + rh * 8 + trow;
                const float* xrow = &xg[((size_t)(n0 + rl) * TT_ + t) * TH_];
                #pragma unroll
                for (int ii = 0; ii < 6; ++ii)
                    xv[mi][ii][rh] = *(const float2*)&xrow[w * 8 + ii * 64 + tcol];
            }

        float acc[2][6][4];
        #pragma unroll
        for (int mi = 0; mi < 2; ++mi)
            #pragma unroll
            for (int ii = 0; ii < 6; ++ii)
                #pragma unroll
                for (int q = 0; q < 4; ++q) acc[mi][ii][q] = 0.f;

        #pragma unroll
        for (int ks = 0; ks < 8; ++ks) {
            uint32_t aHi[2][4], aLo[2][4], bHi[6][2], bLo[6][2];
            #pragma unroll
            for (int mi = 0; mi < 2; ++mi) {
                uint32_t off = (uint32_t)(((mi * 16 + lrow) * WLD + ks * 16 + lk8) * 2);
                ldsm_x4(aHi[mi], hiB + off);
                ldsm_x4(aLo[mi], loB + off);
            }
            #pragma unroll
            for (int ii = 0; ii < 6; ++ii) {
                uint32_t off = (uint32_t)(((w * 8 + ii * 64 + (lb & 7)) * WLD
                                           + ks * 16 + (lb >> 3) * 8) * 2);
                ldsm_x2(bHi[ii], whiB + off);
                ldsm_x2(bLo[ii], wloB + off);
            }
            #pragma unroll
            for (int mi = 0; mi < 2; ++mi)
                #pragma unroll
                for (int ii = 0; ii < 6; ++ii) {
                    mma_bf16(acc[mi][ii], aHi[mi], bHi[ii][0], bHi[ii][1]);
                    mma_bf16(acc[mi][ii], aHi[mi], bLo[ii][0], bLo[ii][1]);
                    mma_bf16(acc[mi][ii], aLo[mi], bHi[ii][0], bHi[ii][1]);
                }
        }
        __syncthreads();

        #pragma unroll
        for (int mi = 0; mi < 2; ++mi)
            #pragma unroll
            for (int ii = 0; ii < 2; ++ii)
                #pragma unroll
                for (int rh = 0; rh < 2; ++rh) {
                    float hn2[2];
                    #pragma unroll
                    for (int cp = 0; cp < 2; ++cp) {
                        int q = rh * 2 + cp;
                        float xr = cp ? xv[mi][ii][rh].y     : xv[mi][ii][rh].x;
                        float xz = cp ? xv[mi][ii + 2][rh].y : xv[mi][ii + 2][rh].x;
                        float xn = cp ? xv[mi][ii + 4][rh].y : xv[mi][ii + 4][rh].x;
                        float hr = acc[mi][ii][q]     + bias[ii][cp];
                        float hz = acc[mi][ii + 2][q] + bias[ii + 2][cp];
                        float hn = acc[mi][ii + 4][q] + bias[ii + 4][cp];
                        float rg = sigf(xr + hr);
                        float zg = sigf(xz + hz);
                        float ng = tanh_ex(xn + rg * hn);
                        float hv = (1.f - zg) * ng + zg * hp[mi][ii][rh][cp];
                        hp[mi][ii][rh][cp] = hv;
                        hn2[cp] = hv;
                    }
                    int rl = mi * 16 + rh * 8 + trow;
                    int j  = w * 8 + ii * 64 + tcol;
                    *(uint32_t*)&Hhi[rl * WLD + j] = pack_bf16(hn2[0], hn2[1]);
                    *(uint32_t*)&Hlo[rl * WLD + j] =
                        pack_bf16(hn2[0] - bf16_rt(hn2[0]), hn2[1] - bf16_rt(hn2[1]));
                    if (hseq)
                        *(float2*)&hseq[((size_t)(n0 + rl) * TT_ + t) * HH_ + j] =
                            make_float2(hn2[0], hn2[1]);
                }
        __syncthreads();
    }

    if (hlast) {
        #pragma unroll
        for (int mi = 0; mi < 2; ++mi)
            #pragma unroll
            for (int ii = 0; ii < 2; ++ii)
                #pragma unroll
                for (int rh = 0; rh < 2; ++rh) {
                    int rl = mi * 16 + rh * 8 + trow;
                    int j  = w * 8 + ii * 64 + tcol;
                    *(float2*)&hlast[(size_t)(n0 + rl) * HH_ + j] =
                        make_float2(hp[mi][ii][rh][0], hp[mi][ii][rh][1]);
                }
    }
}

// ========== scalar SGEMM — for the 3 small [4000x128] GEMMs =====
#define AS_LD 130
#define BS_LD 132
#define GEMM_SMEM ((size_t)(128 * AS_LD + 128 * BS_LD) * 4)

__global__ void __launch_bounds__(256) gemm128(const float* __restrict__ A,
                                               const float* __restrict__ W,
                                               const float* __restrict__ bias,
                                               float* __restrict__ C,
                                               int M, int NNout, int act) {
    extern __shared__ float sm[];
    float* As = sm;
    float* Bs = sm + 128 * AS_LD;
    int tid = threadIdx.x;
    int mBase = blockIdx.x * 128;
    int nBase = blockIdx.y * 128;

    #pragma unroll
    for (int i = 0; i < 16; ++i) {
        int lin = tid + i * 256;
        int m = lin >> 5, k4 = lin & 31;
        float4 v = make_float4(0.f, 0.f, 0.f, 0.f);
        if (mBase + m < M) v = *(const float4*)&A[(size_t)(mBase + m) * 128 + k4 * 4];
        float* dst = &As[m * AS_LD + k4 * 4];
        dst[0] = v.x; dst[1] = v.y; dst[2] = v.z; dst[3] = v.w;
    }
    {
        int ng = tid >> 5, k4 = tid & 31;
        #pragma unroll
        for (int i = 0; i < 4; ++i) {
            int nr = (ng + i * 8) * 4;
            float4 w0 = *(const float4*)&W[(size_t)(nBase + nr + 0) * 128 + k4 * 4];
            float4 w1 = *(const float4*)&W[(size_t)(nBase + nr + 1) * 128 + k4 * 4];
            float4 w2 = *(const float4*)&W[(size_t)(nBase + nr + 2) * 128 + k4 * 4];
            float4 w3 = *(const float4*)&W[(size_t)(nBase + nr + 3) * 128 + k4 * 4];
            *(float4*)&Bs[(k4 * 4 + 0) * BS_LD + nr] = make_float4(w0.x, w1.x, w2.x, w3.x);
            *(float4*)&Bs[(k4 * 4 + 1) * BS_LD + nr] = make_float4(w0.y, w1.y, w2.y, w3.y);
            *(float4*)&Bs[(k4 * 4 + 2) * BS_LD + nr] = make_float4(w0.z, w1.z, w2.z, w3.z);
            *(float4*)&Bs[(k4 * 4 + 3) * BS_LD + nr] = make_float4(w0.w, w1.w, w2.w, w3.w);
        }
    }
    __syncthreads();

    int tx = tid & 15, ty = tid >> 4;
    int c0 = tx * 8, r0 = ty * 8;

    float acc[8][8];
    #pragma unroll
    for (int i = 0; i < 8; ++i)
        #pragma unroll
        for (int j = 0; j < 8; ++j) acc[i][j] = 0.f;

    #pragma unroll 4
    for (int k = 0; k < 128; ++k) {
        float a[8], bb[8];
        #pragma unroll
        for (int i = 0; i < 8; ++i) a[i] = As[(r0 + i) * AS_LD + k];
        float4 b0 = *(const float4*)&Bs[k * BS_LD + c0];
        float4 b1 = *(const float4*)&Bs[k * BS_LD + c0 + 4];
        bb[0] = b0.x; bb[1] = b0.y; bb[2] = b0.z; bb[3] = b0.w;
        bb[4] = b1.x; bb[5] = b1.y; bb[6] = b1.z; bb[7] = b1.w;
        #pragma unroll
        for (int i = 0; i < 8; ++i)
            #pragma unroll
            for (int j = 0; j < 8; ++j) acc[i][j] += a[i] * bb[j];
    }

    float bv[8];
    #pragma unroll
    for (int j = 0; j < 8; ++j) bv[j] = bias ? bias[nBase + c0 + j] : 0.f;

    #pragma unroll
    for (int i = 0; i < 8; ++i) {
        int gm = mBase + r0 + i;
        if (gm >= M) continue;
        float o[8];
        #pragma unroll
        for (int j = 0; j < 8; ++j) {
            o[j] = acc[i][j] + bv[j];
            if (act) o[j] = o[j] > 0.f ? o[j] : 0.01f * o[j];
        }
        *(float4*)&C[(size_t)gm * NNout + nBase + c0]     = make_float4(o[0], o[1], o[2], o[3]);
        *(float4*)&C[(size_t)gm * NNout + nBase + c0 + 4] = make_float4(o[4], o[5], o[6], o[7]);
    }
}

// ====================== parallelized hypergraph tail =========================
__global__ void degrees_kernel(const int* __restrict__ ind, float* __restrict__ inv_dn,
                               float* __restrict__ inv_de) {
    int b = blockIdx.x, tid = threadIdx.x;
    if (b < EE_) {
        __shared__ float red[256];
        int s = 0;
        for (int n = tid; n < NN_; n += 256) s += ind[n * EE_ + b];
        red[tid] = (float)s;
        __syncthreads();
        for (int o = 128; o > 0; o >>= 1) {
            if (tid < o) red[tid] += red[tid + o];
            __syncthreads();
        }
        if (tid == 0) inv_de[b] = red[0] > 0.f ? __fdividef(1.f, red[0]) : 0.f;
    } else {
        int n = (b - EE_) * 256 + tid;
        if (n < NN_) {
            const int4* r = (const int4*)&ind[n * EE_];
            int s = 0;
            #pragma unroll
            for (int i = 0; i < 16; ++i) {
                int4 v = r[i];
                s += v.x + v.y + v.z + v.w;
            }
            inv_dn[n] = s > 0 ? __fdividef(1.f, (float)s) : 0.f;
        }
    }
}

__global__ void prior_m_part(const int* __restrict__ ind, const float* __restrict__ xW,
                             float* __restrict__ m1p) {
    int e = blockIdx.x, ch = blockIdx.y, j = threadIdx.x;
    float acc = 0.f;
    int nA = ch * CHN_;
    #pragma unroll 4
    for (int n = nA; n < nA + CHN_; ++n)
        acc += (float)ind[n * EE_ + e] * xW[n * HH_ + j];
    m1p[(e * NCH_ + ch) * HH_ + j] = acc;
}
__global__ void prior_m_fin(const float* __restrict__ m1p, const float* __restrict__ inv_de,
                            float* __restrict__ m1) {
    int e = blockIdx.x, j = threadIdx.x;
    float a = 0.f;
    #pragma unroll
    for (int c = 0; c < NCH_; ++c) a += m1p[(e * NCH_ + c) * HH_ + j];
    m1[e * HH_ + j] = a * inv_de[e];
}

// fused prior_out + beta: block n computes ep/er row then beta/isdn for same row
__global__ void prior_beta_kernel(const int* __restrict__ ind, const float* __restrict__ m1,
                                  const float* __restrict__ inv_dn, const float* __restrict__ bp,
                                  const float* __restrict__ es, const float* __restrict__ proto,
                                  float* __restrict__ ep, float* __restrict__ er,
                                  float* __restrict__ beta, float* __restrict__ isdn) {
    __shared__ float ms[EE_ * HH_];
    __shared__ float ers[HH_];
    __shared__ float sb[KK_];
    int n = blockIdx.x, j = threadIdx.x;
    for (int i = j; i < EE_ * HH_; i += 128) ms[i] = m1[i];
    __syncthreads();
    float acc = 0.f;
    #pragma unroll 8
    for (int e = 0; e < EE_; ++e)
        acc += (float)ind[n * EE_ + e] * ms[e * HH_ + j];
    float v = acc * inv_dn[n] + bp[j];
    v = v > 0.f ? v : 0.01f * v;
    ep[n * HH_ + j] = v;
    float erv = es[n * HH_ + j] - v;
    er[n * HH_ + j] = erv;
    ers[j] = erv;
    __syncthreads();

    int k = j >> 2, p = j & 3;
    float acc2 = 0.f;
    #pragma unroll 8
    for (int jj = p; jj < HH_; jj += 4)
        acc2 += ers[jj] * __ldg(&proto[k * HH_ + jj]);
    acc2 += __shfl_xor_sync(0xffffffffu, acc2, 1);
    acc2 += __shfl_xor_sync(0xffffffffu, acc2, 2);
    if (p == 0) {
        float bv = sigf(acc2);
        beta[n * KK_ + k] = bv;
        sb[k] = bv;
    }
    __syncthreads();
    if (j < 32) {
        float s = sb[j];
        #pragma unroll
        for (int o = 16; o > 0; o >>= 1) s += __shfl_xor_sync(0xffffffffu, s, o);
        if (j == 0) isdn[n] = s > 0.f ? rsqrtf(s) : 0.f;
    }
}

__global__ void de2_kernel(const float* __restrict__ beta, float* __restrict__ inv_de2) {
    int k = blockIdx.x, tid = threadIdx.x;
    float s = 0.f;
    for (int n = tid; n < NN_; n += 256) s += beta[n * KK_ + k];
    __shared__ float red[256];
    red[tid] = s;
    __syncthreads();
    for (int o = 128; o > 0; o >>= 1) {
        if (tid < o) red[tid] += red[tid + o];
        __syncthreads();
    }
    if (tid == 0) inv_de2[k] = red[0] > 0.f ? __fdividef(1.f, red[0]) : 0.f;
}

__global__ void soft_m_part(const float* __restrict__ beta, const float* __restrict__ y,
                            float* __restrict__ m2p) {
    int k = blockIdx.x, ch = blockIdx.y, j = threadIdx.x;
    float acc = 0.f;
    int nA = ch * CHN_;
    #pragma unroll 4
    for (int n = nA; n < nA + CHN_; ++n)
        acc += beta[n * KK_ + k] * y[n * HH_ + j];
    m2p[(k * NCH_ + ch) * HH_ + j] = acc;
}
__global__ void soft_m_fin(const float* __restrict__ m2p, const float* __restrict__ inv_de2,
                           float* __restrict__ m2) {
    int k = blockIdx.x, j = threadIdx.x;
    float a = 0.f;
    #pragma unroll
    for (int c = 0; c < NCH_; ++c) a += m2p[(k * NCH_ + c) * HH_ + j];
    m2[k * HH_ + j] = a * inv_de2[k];
}

__global__ void soft_out_kernel(const float* __restrict__ beta, const float* __restrict__ m2,
                                const float* __restrict__ isdn, const float* __restrict__ er,
                                float* __restrict__ eh, float* __restrict__ eres) {
    __shared__ float ms[KK_ * HH_];
    __shared__ float bsh[KK_];
    int n = blockIdx.x, j = threadIdx.x;
    for (int i = j; i < KK_ * HH_; i += 128) ms[i] = m2[i];
    if (j < KK_) bsh[j] = beta[n * KK_ + j];
    __syncthreads();
    float acc = 0.f;
    #pragma unroll
    for (int k = 0; k < KK_; ++k) acc += bsh[k] * ms[k * HH_ + j];
    float v = acc * isdn[n];
    v = v > 0.f ? v : 0.01f * v;
    eh[n * HH_ + j] = v;
    eres[n * HH_ + j] = er[n * HH_ + j] - v;
}

__global__ void final_kernel(const float* __restrict__ ep, const float* __restrict__ eh,
                             const float* __restrict__ ea, const float* __restrict__ Wf,
                             const float* __restrict__ bf, float* __restrict__ out) {
    int n = blockIdx.x, j = threadIdx.x;
    float v = ep[n * HH_ + j] * Wf[j] + eh[n * HH_ + j] * Wf[128 + j] +
              ea[n * HH_ + j] * Wf[256 + j];
    #pragma unroll
    for (int o = 16; o > 0; o >>= 1) v += __shfl_xor_sync(0xffffffffu, v, o);
    __shared__ float red[4];
    if ((j & 31) == 0) red[j >> 5] = v;
    __syncthreads();
    if (j == 0) out[n] = red[0] + red[1] + red[2] + red[3] + bf[0];
}

// ================================ launch ======================================
extern "C" void kernel_launch(void* const* d_in, const int* in_sizes, int n_in,
                              void* d_out, int out_size) {
    const float* x     = (const float*)d_in[0];
    const int*   ind   = (const int*)  d_in[1];
    const float* ln_g  = (const float*)d_in[2];
    const float* ln_b  = (const float*)d_in[3];
    const float* W_ih0 = (const float*)d_in[4];
    const float* W_hh0 = (const float*)d_in[5];
    const float* b_ih0 = (const float*)d_in[6];
    const float* b_hh0 = (const float*)d_in[7];
    const float* W_ih1 = (const float*)d_in[8];
    const float* W_hh1 = (const float*)d_in[9];
    const float* b_ih1 = (const float*)d_in[10];
    const float* b_hh1 = (const float*)d_in[11];
    const float* Wp    = (const float*)d_in[12];
    const float* bp    = (const float*)d_in[13];
    const float* proto = (const float*)d_in[14];
    const float* Ws    = (const float*)d_in[15];
    const float* bs    = (const float*)d_in[16];
    const float* Wa    = (const float*)d_in[17];
    const float* ba    = (const float*)d_in[18];
    const float* Wf    = (const float*)d_in[19];
    const float* bf    = (const float*)d_in[20];
    float* out = (float*)d_out;

    cudaFuncSetAttribute(gemm128,      cudaFuncAttributeMaxDynamicSharedMemorySize, (int)GEMM_SMEM);
    cudaFuncSetAttribute(gemm_mma,     cudaFuncAttributeMaxDynamicSharedMemorySize, (int)MMA_SMEM);
    cudaFuncSetAttribute(gru_scan_mma, cudaFuncAttributeMaxDynamicSharedMemorySize, (int)SCAN2_SMEM);

    float *xg, *h1, *es, *t1, *ep, *er, *eh, *eres, *ea, *beta, *m1, *m2;
    float *m1p, *m2p, *idn, *ide, *isdn, *ide2;
    cudaGetSymbolAddress((void**)&xg,  g_xg);
    cudaGetSymbolAddress((void**)&h1,  g_h1);
    cudaGetSymbolAddress((void**)&es,  g_es);
    cudaGetSymbolAddress((void**)&t1,  g_t1);
    cudaGetSymbolAddress((void**)&ep,  g_ep);
    cudaGetSymbolAddress((void**)&er,  g_er);
    cudaGetSymbolAddress((void**)&eh,  g_eh);
    cudaGetSymbolAddress((void**)&eres,g_eres);
    cudaGetSymbolAddress((void**)&ea,  g_ea);
    cudaGetSymbolAddress((void**)&beta,g_beta);
    cudaGetSymbolAddress((void**)&m1,  g_m1);
    cudaGetSymbolAddress((void**)&m2,  g_m2);
    cudaGetSymbolAddress((void**)&m1p, g_m1p);
    cudaGetSymbolAddress((void**)&m2p, g_m2p);
    cudaGetSymbolAddress((void**)&idn, g_idn);
    cudaGetSymbolAddress((void**)&ide, g_ide);
    cudaGetSymbolAddress((void**)&isdn,g_isdn);
    cudaGetSymbolAddress((void**)&ide2,g_ide2);

    const int MROWS = NN_ * TT_;   // 256000

    gemm_mma<<<MROWS / 128, 256, MMA_SMEM>>>(x, W_ih0, b_ih0, xg, 1, ln_g, ln_b);
    gru_scan_mma<<<NN_ / 32, 256, SCAN2_SMEM>>>(xg, W_hh0, b_hh0, h1, nullptr);
    gemm_mma<<<MROWS / 128, 256, MMA_SMEM>>>(h1, W_ih1, b_ih1, xg, 0, ln_g, ln_b);
    gru_scan_mma<<<NN_ / 32, 256, SCAN2_SMEM>>>(xg, W_hh1, b_hh1, nullptr, es);
    gemm128<<<dim3((NN_ + 127) / 128, 1), 256, GEMM_SMEM>>>(es, Wp, nullptr, t1, NN_, HH_, 0);
    degrees_kernel<<<EE_ + (NN_ + 255) / 256, 256>>>(ind, idn, ide);
    prior_m_part<<<dim3(EE_, NCH_), 128>>>(ind, t1, m1p);
    prior_m_fin<<<EE_, 128>>>(m1p, ide, m1);
    prior_beta_kernel<<<NN_, 128>>>(ind, m1, idn, bp, es, proto, ep, er, beta, isdn);
    de2_kernel<<<KK_, 256>>>(beta, ide2);
    gemm128<<<dim3((NN_ + 127) / 128, 1), 256, GEMM_SMEM>>>(er, Ws, bs, t1, NN_, HH_, 0);
    soft_m_part<<<dim3(KK_, NCH_), 128>>>(beta, t1, m2p);
    soft_m_fin<<<KK_, 128>>>(m2p, ide2, m2);
    soft_out_kernel<<<NN_, 128>>>(beta, m2, isdn, er, eh, eres);
    gemm128<<<dim3((NN_ + 127) / 128, 1), 256, GEMM_SMEM>>>(eres, Wa, ba, ea, NN_, HH_, 1);
    final_kernel<<<NN_, 128>>>(ep, eh, ea, Wf, bf, out);
}

// round 17
// speedup vs baseline: 1.0931x; 1.0931x over previous
#include <cuda_runtime.h>
#include <cuda_bf16.h>
#include <cstddef>
#include <cstdint>

#define NN_   4000
#define TT_   64
#define FF_   128
#define HH_   128
#define TH_   384
#define KK_   32
#define EE_   64
#define NCH_  8
#define CHN_  (NN_ / NCH_)   // 500

// ---------------- scratch (static device globals; no allocation) --------------
__device__ float g_xg [(size_t)NN_ * TT_ * TH_];
__device__ float g_h1 [(size_t)NN_ * TT_ * HH_];
__device__ float g_es [NN_ * HH_];
__device__ float g_t1 [NN_ * HH_];
__device__ float g_ep [NN_ * HH_];
__device__ float g_er [NN_ * HH_];
__device__ float g_eh [NN_ * HH_];
__device__ float g_eres[NN_ * HH_];
__device__ float g_ea [NN_ * HH_];
__device__ float g_beta[NN_ * KK_];
__device__ float g_m1 [EE_ * HH_];
__device__ float g_m2 [KK_ * HH_];
__device__ float g_m1p[EE_ * NCH_ * HH_];
__device__ float g_m2p[KK_ * NCH_ * HH_];
__device__ float g_idn [NN_];
__device__ float g_ide [EE_];
__device__ float g_isdn[NN_];
__device__ float g_ide2[KK_];

// ---------------- helpers ----------------
__device__ __forceinline__ float sigf(float x) {
    return __fdividef(1.f, 1.f + __expf(-x));
}
__device__ __forceinline__ float tanh_ex(float x) {
    return __fdividef(2.f, 1.f + __expf(-2.f * x)) - 1.f;
}
__device__ __forceinline__ uint32_t smem_u32(const void* p) {
    uint32_t a;
    asm("{ .reg .u64 t; cvta.to.shared.u64 t, %1; cvt.u32.u64 %0, t; }" : "=r"(a) : "l"(p));
    return a;
}
__device__ __forceinline__ uint32_t pack_bf16(float a, float b) {
    __nv_bfloat162 t = __floats2bfloat162_rn(a, b);
    return *(uint32_t*)&t;
}
__device__ __forceinline__ float bf16_rt(float v) {
    return __bfloat162float(__float2bfloat16_rn(v));
}
__device__ __forceinline__ void ldsm_x4(uint32_t* r, uint32_t addr) {
    asm volatile("ldmatrix.sync.aligned.m8n8.x4.shared.b16 {%0,%1,%2,%3}, [%4];"
                 : "=r"(r[0]), "=r"(r[1]), "=r"(r[2]), "=r"(r[3]) : "r"(addr));
}
__device__ __forceinline__ void ldsm_x2(uint32_t* r, uint32_t addr) {
    asm volatile("ldmatrix.sync.aligned.m8n8.x2.shared.b16 {%0,%1}, [%2];"
                 : "=r"(r[0]), "=r"(r[1]) : "r"(addr));
}
__device__ __forceinline__ void mma_bf16(float* d, const uint32_t* a,
                                         uint32_t b0, uint32_t b1) {
    asm volatile(
        "mma.sync.aligned.m16n8k16.row.col.f32.bf16.bf16.f32 "
        "{%0,%1,%2,%3}, {%4,%5,%6,%7}, {%8,%9}, {%0,%1,%2,%3};"
        : "+f"(d[0]), "+f"(d[1]), "+f"(d[2]), "+f"(d[3])
        : "r"(a[0]), "r"(a[1]), "r"(a[2]), "r"(a[3]), "r"(b0), "r"(b1));
}

// ============ mma.sync big GEMM: 512 threads, 4x4 warp grid (32x32 tiles) =====
#define LDPAD 136
#define MMA_SMEM (4 * 128 * LDPAD * 2)

__global__ void __launch_bounds__(512) gemm_mma(const float* __restrict__ A,
                                                const float* __restrict__ W,
                                                const float* __restrict__ bias,
                                                float* __restrict__ C,
                                                int do_ln,
                                                const float* __restrict__ ln_g,
                                                const float* __restrict__ ln_b) {
    extern __shared__ char smem[];
    __nv_bfloat16* As1 = (__nv_bfloat16*)smem;        // [128][LDPAD]
    __nv_bfloat16* As2 = As1 + 128 * LDPAD;
    __nv_bfloat16* Ws1 = As2 + 128 * LDPAD;
    __nv_bfloat16* Ws2 = Ws1 + 128 * LDPAD;
    int tid = threadIdx.x;
    int lane = tid & 31;
    int mBase = blockIdx.x * 128;

    float4 gv = make_float4(1.f, 1.f, 1.f, 1.f), bv4 = make_float4(0.f, 0.f, 0.f, 0.f);
    if (do_ln) {
        gv  = *(const float4*)&ln_g[lane * 4];
        bv4 = *(const float4*)&ln_b[lane * 4];
    }

    // stage A (4096 float4 slots / 512 threads = 8 iters; warp = one row/iter)
    #pragma unroll 2
    for (int i = 0; i < 8; ++i) {
        int lin = tid + i * 512;
        int row = lin >> 5, c4 = (lin & 31) * 4;
        float4 v = *(const float4*)&A[(size_t)(mBase + row) * 128 + c4];
        if (do_ln) {
            float s  = v.x + v.y + v.z + v.w;
            float ss = v.x * v.x + v.y * v.y + v.z * v.z + v.w * v.w;
            #pragma unroll
            for (int o = 16; o > 0; o >>= 1) {
                s  += __shfl_xor_sync(0xffffffffu, s,  o);
                ss += __shfl_xor_sync(0xffffffffu, ss, o);
            }
            float mean = s * (1.f / 128.f);
            float var  = ss * (1.f / 128.f) - mean * mean;
            float rstd = rsqrtf(var + 1e-5f);
            v.x = (v.x - mean) * rstd * gv.x + bv4.x;
            v.y = (v.y - mean) * rstd * gv.y + bv4.y;
            v.z = (v.z - mean) * rstd * gv.z + bv4.z;
            v.w = (v.w - mean) * rstd * gv.w + bv4.w;
        }
        *(uint2*)&As1[row * LDPAD + c4] = make_uint2(pack_bf16(v.x, v.y), pack_bf16(v.z, v.w));
        *(uint2*)&As2[row * LDPAD + c4] =
            make_uint2(pack_bf16(v.x - bf16_rt(v.x), v.y - bf16_rt(v.y)),
                       pack_bf16(v.z - bf16_rt(v.z), v.w - bf16_rt(v.w)));
    }

    int wid = tid >> 5, l = lane;
    int wm = wid >> 2, wn = wid & 3;              // 4x4 warp grid
    int lrow = (l & 7) + ((l >> 3) & 1) * 8;
    int lk8  = (l >> 4) * 8;
    int trow = l >> 2, tcol = (l & 3) * 2;

    uint32_t aB1 = smem_u32(As1), aB2 = smem_u32(As2);
    uint32_t wB1 = smem_u32(Ws1), wB2 = smem_u32(Ws2);

    for (int nc = 0; nc < 3; ++nc) {
        if (nc > 0) __syncthreads();
        #pragma unroll 2
        for (int i = 0; i < 8; ++i) {
            int lin = tid + i * 512;
            int row = lin >> 5, c4 = (lin & 31) * 4;
            float4 w = *(const float4*)&W[(size_t)(nc * 128 + row) * 128 + c4];
            *(uint2*)&Ws1[row * LDPAD + c4] =
                make_uint2(pack_bf16(w.x, w.y), pack_bf16(w.z, w.w));
            *(uint2*)&Ws2[row * LDPAD + c4] =
                make_uint2(pack_bf16(w.x - bf16_rt(w.x), w.y - bf16_rt(w.y)),
                           pack_bf16(w.z - bf16_rt(w.z), w.w - bf16_rt(w.w)));
        }
        __syncthreads();

        float acc[2][4][4];
        #pragma unroll
        for (int mi = 0; mi < 2; ++mi)
            #pragma unroll
            for (int ni = 0; ni < 4; ++ni)
                #pragma unroll
                for (int q = 0; q < 4; ++q) acc[mi][ni][q] = 0.f;

        uint32_t apass[3] = {aB1, aB2, aB1};
        uint32_t wpass[3] = {wB1, wB1, wB2};
        #pragma unroll
        for (int pass = 0; pass < 3; ++pass) {
            uint32_t ab = apass[pass], bb = wpass[pass];
            #pragma unroll
            for (int ks = 0; ks < 8; ++ks) {
                int k0 = ks * 16;
                uint32_t a[2][4], b[2][4];
                #pragma unroll
                for (int mi = 0; mi < 2; ++mi) {
                    int row = wm * 32 + mi * 16 + lrow;
                    ldsm_x4(a[mi], ab + (uint32_t)(row * LDPAD + k0 + lk8) * 2);
                }
                #pragma unroll
                for (int p = 0; p < 2; ++p) {
                    int nr = wn * 32 + p * 16 + lrow;
                    ldsm_x4(b[p], bb + (uint32_t)(nr * LDPAD + k0 + lk8) * 2);
                }
                #pragma unroll
                for (int mi = 0; mi < 2; ++mi)
                    #pragma unroll
                    for (int ni = 0; ni < 4; ++ni) {
                        int p = ni >> 1, hi = ni & 1;
                        mma_bf16(acc[mi][ni], a[mi], b[p][hi], b[p][hi + 2]);
                    }
            }
        }

        int nBase = nc * 128;
        float bvx[4], bvy[4];
        #pragma unroll
        for (int ni = 0; ni < 4; ++ni) {
            int col = nBase + wn * 32 + ni * 8 + tcol;
            bvx[ni] = bias[col];
            bvy[ni] = bias[col + 1];
        }
        #pragma unroll
        for (int mi = 0; mi < 2; ++mi) {
            size_t row0 = (size_t)mBase + wm * 32 + mi * 16 + trow;
            #pragma unroll
            for (int ni = 0; ni < 4; ++ni) {
                int col = nBase + wn * 32 + ni * 8 + tcol;
                *(float2*)&C[row0 * TH_ + col] =
                    make_float2(acc[mi][ni][0] + bvx[ni], acc[mi][ni][1] + bvy[ni]);
                *(float2*)&C[(row0 + 8) * TH_ + col] =
                    make_float2(acc[mi][ni][2] + bvx[ni], acc[mi][ni][3] + bvy[ni]);
            }
        }
    }
}

// ========== mma.sync GRU scan: 512 threads, warp w owns col-group w*8 =========
// Warp w owns n8-tiles {w, w+16, w+32} = column j=w*8 of gates r/z/n.
#define WLD 136
#define SCAN2_SMEM ((384 * WLD * 2 + 32 * WLD * 2) * 2)   // 226304 bytes

__global__ void __launch_bounds__(512) gru_scan_mma(const float* __restrict__ xg,
                                                    const float* __restrict__ Whh,
                                                    const float* __restrict__ bhh,
                                                    float* __restrict__ hseq,
                                                    float* __restrict__ hlast) {
    extern __shared__ char smraw[];
    __nv_bfloat16* Whi = (__nv_bfloat16*)smraw;    // [384][WLD]
    __nv_bfloat16* Wlo = Whi + 384 * WLD;
    __nv_bfloat16* Hhi = Wlo + 384 * WLD;          // [32][WLD]
    __nv_bfloat16* Hlo = Hhi + 32 * WLD;
    int tid = threadIdx.x;

    #pragma unroll 4
    for (int i = 0; i < 24; ++i) {
        int lin = tid + i * 512;                   // 12288 float4 slots
        int row = lin >> 5, c4 = (lin & 31) * 4;
        float4 v = *(const float4*)&Whh[row * 128 + c4];
        *(uint2*)&Whi[row * WLD + c4] = make_uint2(pack_bf16(v.x, v.y), pack_bf16(v.z, v.w));
        *(uint2*)&Wlo[row * WLD + c4] =
            make_uint2(pack_bf16(v.x - bf16_rt(v.x), v.y - bf16_rt(v.y)),
                       pack_bf16(v.z - bf16_rt(v.z), v.w - bf16_rt(v.w)));
    }
    for (int i = tid; i < 32 * WLD / 2; i += 512) {
        ((uint32_t*)Hhi)[i] = 0u;
        ((uint32_t*)Hlo)[i] = 0u;
    }

    int w = tid >> 5, l = tid & 31;                // w in 0..15
    int trow = l >> 2, tcol = (l & 3) * 2;
    int lrow = (l & 7) + ((l >> 3) & 1) * 8;
    int lk8  = (l >> 4) * 8;
    int lb   = l & 15;
    int n0 = blockIdx.x * 32;
    uint32_t hiB = smem_u32(Hhi), loB = smem_u32(Hlo);
    uint32_t whiB = smem_u32(Whi), wloB = smem_u32(Wlo);

    float bias[3][2];
    #pragma unroll
    for (int g = 0; g < 3; ++g) {
        bias[g][0] = bhh[g * 128 + w * 8 + tcol];
        bias[g][1] = bhh[g * 128 + w * 8 + tcol + 1];
    }
    float hp[2][2][2];                             // [mi][rh][cp]
    #pragma unroll
    for (int mi = 0; mi < 2; ++mi)
        #pragma unroll
        for (int rh = 0; rh < 2; ++rh) {
            hp[mi][rh][0] = 0.f;
            hp[mi][rh][1] = 0.f;
        }
    __syncthreads();

    for (int t = 0; t < TT_; ++t) {
        float2 xv[2][3][2];                        // [mi][gate][rh]
        #pragma unroll
        for (int mi = 0; mi < 2; ++mi)
            #pragma unroll
            for (int rh = 0; rh < 2; ++rh) {
                int rl = mi * 16 + rh * 8 + trow;
                const float* xrow = &xg[((size_t)(n0 + rl) * TT_ + t) * TH_];
                #pragma unroll
                for (int g = 0; g < 3; ++g)
                    xv[mi][g][rh] = *(const float2*)&xrow[g * 128 + w * 8 + tcol];
            }

        float acc[2][3][4];
        #pragma unroll
        for (int mi = 0; mi < 2; ++mi)
            #pragma unroll
            for (int g = 0; g < 3; ++g)
                #pragma unroll
                for (int q = 0; q < 4; ++q) acc[mi][g][q] = 0.f;

        #pragma unroll
        for (int ks = 0; ks < 8; ++ks) {
            uint32_t aHi[2][4], aLo[2][4], bHi[3][2], bLo[3][2];
            #pragma unroll
            for (int mi = 0; mi < 2; ++mi) {
                uint32_t off = (uint32_t)(((mi * 16 + lrow) * WLD + ks * 16 + lk8) * 2);
                ldsm_x4(aHi[mi], hiB + off);
                ldsm_x4(aLo[mi], loB + off);
            }
            #pragma unroll
            for (int g = 0; g < 3; ++g) {
                uint32_t off = (uint32_t)(((g * 128 + w * 8 + (lb & 7)) * WLD
                                           + ks * 16 + (lb >> 3) * 8) * 2);
                ldsm_x2(bHi[g], whiB + off);
                ldsm_x2(bLo[g], wloB + off);
            }
            #pragma unroll
            for (int mi = 0; mi < 2; ++mi)
                #pragma unroll
                for (int g = 0; g < 3; ++g) {
                    mma_bf16(acc[mi][g], aHi[mi], bHi[g][0], bHi[g][1]);
                    mma_bf16(acc[mi][g], aHi[mi], bLo[g][0], bLo[g][1]);
                    mma_bf16(acc[mi][g], aLo[mi], bHi[g][0], bHi[g][1]);
                }
        }
        __syncthreads();   // all warps done reading H

        #pragma unroll
        for (int mi = 0; mi < 2; ++mi)
            #pragma unroll
            for (int rh = 0; rh < 2; ++rh) {
                float hn2[2];
                #pragma unroll
                for (int cp = 0; cp < 2; ++cp) {
                    int q = rh * 2 + cp;
                    float xr = cp ? xv[mi][0][rh].y : xv[mi][0][rh].x;
                    float xz = cp ? xv[mi][1][rh].y : xv[mi][1][rh].x;
                    float xn = cp ? xv[mi][2][rh].y : xv[mi][2][rh].x;
                    float hr = acc[mi][0][q] + bias[0][cp];
                    float hz = acc[mi][1][q] + bias[1][cp];
                    float hn = acc[mi][2][q] + bias[2][cp];
                    float rg = sigf(xr + hr);
                    float zg = sigf(xz + hz);
                    float ng = tanh_ex(xn + rg * hn);
                    float hv = (1.f - zg) * ng + zg * hp[mi][rh][cp];
                    hp[mi][rh][cp] = hv;
                    hn2[cp] = hv;
                }
                int rl = mi * 16 + rh * 8 + trow;
                int j  = w * 8 + tcol;
                *(uint32_t*)&Hhi[rl * WLD + j] = pack_bf16(hn2[0], hn2[1]);
                *(uint32_t*)&Hlo[rl * WLD + j] =
                    pack_bf16(hn2[0] - bf16_rt(hn2[0]), hn2[1] - bf16_rt(hn2[1]));
                if (hseq)
                    *(float2*)&hseq[((size_t)(n0 + rl) * TT_ + t) * HH_ + j] =
                        make_float2(hn2[0], hn2[1]);
            }
        __syncthreads();   // H update visible to next step
    }

    if (hlast) {
        #pragma unroll
        for (int mi = 0; mi < 2; ++mi)
            #pragma unroll
            for (int rh = 0; rh < 2; ++rh) {
                int rl = mi * 16 + rh * 8 + trow;
                int j  = w * 8 + tcol;
                *(float2*)&hlast[(size_t)(n0 + rl) * HH_ + j] =
                    make_float2(hp[mi][rh][0], hp[mi][rh][1]);
            }
    }
}

// ========== scalar SGEMM — for the 3 small [4000x128] GEMMs =====
#define AS_LD 130
#define BS_LD 132
#define GEMM_SMEM ((size_t)(128 * AS_LD + 128 * BS_LD) * 4)

__global__ void __launch_bounds__(256) gemm128(const float* __restrict__ A,
                                               const float* __restrict__ W,
                                               const float* __restrict__ bias,
                                               float* __restrict__ C,
                                               int M, int NNout, int act) {
    extern __shared__ float sm[];
    float* As = sm;
    float* Bs = sm + 128 * AS_LD;
    int tid = threadIdx.x;
    int mBase = blockIdx.x * 128;
    int nBase = blockIdx.y * 128;

    #pragma unroll
    for (int i = 0; i < 16; ++i) {
        int lin = tid + i * 256;
        int m = lin >> 5, k4 = lin & 31;
        float4 v = make_float4(0.f, 0.f, 0.f, 0.f);
        if (mBase + m < M) v = *(const float4*)&A[(size_t)(mBase + m) * 128 + k4 * 4];
        float* dst = &As[m * AS_LD + k4 * 4];
        dst[0] = v.x; dst[1] = v.y; dst[2] = v.z; dst[3] = v.w;
    }
    {
        int ng = tid >> 5, k4 = tid & 31;
        #pragma unroll
        for (int i = 0; i < 4; ++i) {
            int nr = (ng + i * 8) * 4;
            float4 w0 = *(const float4*)&W[(size_t)(nBase + nr + 0) * 128 + k4 * 4];
            float4 w1 = *(const float4*)&W[(size_t)(nBase + nr + 1) * 128 + k4 * 4];
            float4 w2 = *(const float4*)&W[(size_t)(nBase + nr + 2) * 128 + k4 * 4];
            float4 w3 = *(const float4*)&W[(size_t)(nBase + nr + 3) * 128 + k4 * 4];
            *(float4*)&Bs[(k4 * 4 + 0) * BS_LD + nr] = make_float4(w0.x, w1.x, w2.x, w3.x);
            *(float4*)&Bs[(k4 * 4 + 1) * BS_LD + nr] = make_float4(w0.y, w1.y, w2.y, w3.y);
            *(float4*)&Bs[(k4 * 4 + 2) * BS_LD + nr] = make_float4(w0.z, w1.z, w2.z, w3.z);
            *(float4*)&Bs[(k4 * 4 + 3) * BS_LD + nr] = make_float4(w0.w, w1.w, w2.w, w3.w);
        }
    }
    __syncthreads();

    int tx = tid & 15, ty = tid >> 4;
    int c0 = tx * 8, r0 = ty * 8;

    float acc[8][8];
    #pragma unroll
    for (int i = 0; i < 8; ++i)
        #pragma unroll
        for (int j = 0; j < 8; ++j) acc[i][j] = 0.f;

    #pragma unroll 4
    for (int k = 0; k < 128; ++k) {
        float a[8], bb[8];
        #pragma unroll
        for (int i = 0; i < 8; ++i) a[i] = As[(r0 + i) * AS_LD + k];
        float4 b0 = *(const float4*)&Bs[k * BS_LD + c0];
        float4 b1 = *(const float4*)&Bs[k * BS_LD + c0 + 4];
        bb[0] = b0.x; bb[1] = b0.y; bb[2] = b0.z; bb[3] = b0.w;
        bb[4] = b1.x; bb[5] = b1.y; bb[6] = b1.z; bb[7] = b1.w;
        #pragma unroll
        for (int i = 0; i < 8; ++i)
            #pragma unroll
            for (int j = 0; j < 8; ++j) acc[i][j] += a[i] * bb[j];
    }

    float bv[8];
    #pragma unroll
    for (int j = 0; j < 8; ++j) bv[j] = bias ? bias[nBase + c0 + j] : 0.f;

    #pragma unroll
    for (int i = 0; i < 8; ++i) {
        int gm = mBase + r0 + i;
        if (gm >= M) continue;
        float o[8];
        #pragma unroll
        for (int j = 0; j < 8; ++j) {
            o[j] = acc[i][j] + bv[j];
            if (act) o[j] = o[j] > 0.f ? o[j] : 0.01f * o[j];
        }
        *(float4*)&C[(size_t)gm * NNout + nBase + c0]     = make_float4(o[0], o[1], o[2], o[3]);
        *(float4*)&C[(size_t)gm * NNout + nBase + c0 + 4] = make_float4(o[4], o[5], o[6], o[7]);
    }
}

// ====================== parallelized hypergraph tail =========================
__global__ void degrees_kernel(const int* __restrict__ ind, float* __restrict__ inv_dn,
                               float* __restrict__ inv_de) {
    int b = blockIdx.x, tid = threadIdx.x;
    if (b < EE_) {
        __shared__ float red[256];
        int s = 0;
        for (int n = tid; n < NN_; n += 256) s += ind[n * EE_ + b];
        red[tid] = (float)s;
        __syncthreads();
        for (int o = 128; o > 0; o >>= 1) {
            if (tid < o) red[tid] += red[tid + o];
            __syncthreads();
        }
        if (tid == 0) inv_de[b] = red[0] > 0.f ? __fdividef(1.f, red[0]) : 0.f;
    } else {
        int n = (b - EE_) * 256 + tid;
        if (n < NN_) {
            const int4* r = (const int4*)&ind[n * EE_];
            int s = 0;
            #pragma unroll
            for (int i = 0; i < 16; ++i) {
                int4 v = r[i];
                s += v.x + v.y + v.z + v.w;
            }
            inv_dn[n] = s > 0 ? __fdividef(1.f, (float)s) : 0.f;
        }
    }
}

__global__ void prior_m_part(const int* __restrict__ ind, const float* __restrict__ xW,
                             float* __restrict__ m1p) {
    int e = blockIdx.x, ch = blockIdx.y, j = threadIdx.x;
    float acc = 0.f;
    int nA = ch * CHN_;
    #pragma unroll 4
    for (int n = nA; n < nA + CHN_; ++n)
        acc += (float)ind[n * EE_ + e] * xW[n * HH_ + j];
    m1p[(e * NCH_ + ch) * HH_ + j] = acc;
}
__global__ void prior_m_fin(const float* __restrict__ m1p, const float* __restrict__ inv_de,
                            float* __restrict__ m1) {
    int e = blockIdx.x, j = threadIdx.x;
    float a = 0.f;
    #pragma unroll
    for (int c = 0; c < NCH_; ++c) a += m1p[(e * NCH_ + c) * HH_ + j];
    m1[e * HH_ + j] = a * inv_de[e];
}

// fused prior_out + beta
__global__ void prior_beta_kernel(const int* __restrict__ ind, const float* __restrict__ m1,
                                  const float* __restrict__ inv_dn, const float* __restrict__ bp,
                                  const float* __restrict__ es, const float* __restrict__ proto,
                                  float* __restrict__ ep, float* __restrict__ er,
                                  float* __restrict__ beta, float* __restrict__ isdn) {
    __shared__ float ms[EE_ * HH_];
    __shared__ float ers[HH_];
    __shared__ float sb[KK_];
    int n = blockIdx.x, j = threadIdx.x;
    for (int i = j; i < EE_ * HH_; i += 128) ms[i] = m1[i];
    __syncthreads();
    float acc = 0.f;
    #pragma unroll 8
    for (int e = 0; e < EE_; ++e)
        acc += (float)ind[n * EE_ + e] * ms[e * HH_ + j];
    float v = acc * inv_dn[n] + bp[j];
    v = v > 0.f ? v : 0.01f * v;
    ep[n * HH_ + j] = v;
    float erv = es[n * HH_ + j] - v;
    er[n * HH_ + j] = erv;
    ers[j] = erv;
    __syncthreads();

    int k = j >> 2, p = j & 3;
    float acc2 = 0.f;
    #pragma unroll 8
    for (int jj = p; jj < HH_; jj += 4)
        acc2 += ers[jj] * __ldg(&proto[k * HH_ + jj]);
    acc2 += __shfl_xor_sync(0xffffffffu, acc2, 1);
    acc2 += __shfl_xor_sync(0xffffffffu, acc2, 2);
    if (p == 0) {
        float bv = sigf(acc2);
        beta[n * KK_ + k] = bv;
        sb[k] = bv;
    }
    __syncthreads();
    if (j < 32) {
        float s = sb[j];
        #pragma unroll
        for (int o = 16; o > 0; o >>= 1) s += __shfl_xor_sync(0xffffffffu, s, o);
        if (j == 0) isdn[n] = s > 0.f ? rsqrtf(s) : 0.f;
    }
}

__global__ void de2_kernel(const float* __restrict__ beta, float* __restrict__ inv_de2) {
    int k = blockIdx.x, tid = threadIdx.x;
    float s = 0.f;
    for (int n = tid; n < NN_; n += 256) s += beta[n * KK_ + k];
    __shared__ float red[256];
    red[tid] = s;
    __syncthreads();
    for (int o = 128; o > 0; o >>= 1) {
        if (tid < o) red[tid] += red[tid + o];
        __syncthreads();
    }
    if (tid == 0) inv_de2[k] = red[0] > 0.f ? __fdividef(1.f, red[0]) : 0.f;
}

__global__ void soft_m_part(const float* __restrict__ beta, const float* __restrict__ y,
                            float* __restrict__ m2p) {
    int k = blockIdx.x, ch = blockIdx.y, j = threadIdx.x;
    float acc = 0.f;
    int nA = ch * CHN_;
    #pragma unroll 4
    for (int n = nA; n < nA + CHN_; ++n)
        acc += beta[n * KK_ + k] * y[n * HH_ + j];
    m2p[(k * NCH_ + ch) * HH_ + j] = acc;
}
__global__ void soft_m_fin(const float* __restrict__ m2p, const float* __restrict__ inv_de2,
                           float* __restrict__ m2) {
    int k = blockIdx.x, j = threadIdx.x;
    float a = 0.f;
    #pragma unroll
    for (int c = 0; c < NCH_; ++c) a += m2p[(k * NCH_ + c) * HH_ + j];
    m2[k * HH_ + j] = a * inv_de2[k];
}

__global__ void soft_out_kernel(const float* __restrict__ beta, const float* __restrict__ m2,
                                const float* __restrict__ isdn, const float* __restrict__ er,
                                float* __restrict__ eh, float* __restrict__ eres) {
    __shared__ float ms[KK_ * HH_];
    __shared__ float bsh[KK_];
    int n = blockIdx.x, j = threadIdx.x;
    for (int i = j; i < KK_ * HH_; i += 128) ms[i] = m2[i];
    if (j < KK_) bsh[j] = beta[n * KK_ + j];
    __syncthreads();
    float acc = 0.f;
    #pragma unroll
    for (int k = 0; k < KK_; ++k) acc += bsh[k] * ms[k * HH_ + j];
    float v = acc * isdn[n];
    v = v > 0.f ? v : 0.01f * v;
    eh[n * HH_ + j] = v;
    eres[n * HH_ + j] = er[n * HH_ + j] - v;
}

__global__ void final_kernel(const float* __restrict__ ep, const float* __restrict__ eh,
                             const float* __restrict__ ea, const float* __restrict__ Wf,
                             const float* __restrict__ bf, float* __restrict__ out) {
    int n = blockIdx.x, j = threadIdx.x;
    float v = ep[n * HH_ + j] * Wf[j] + eh[n * HH_ + j] * Wf[128 + j] +
              ea[n * HH_ + j] * Wf[256 + j];
    #pragma unroll
    for (int o = 16; o > 0; o >>= 1) v += __shfl_xor_sync(0xffffffffu, v, o);
    __shared__ float red[4];
    if ((j & 31) == 0) red[j >> 5] = v;
    __syncthreads();
    if (j == 0) out[n] = red[0] + red[1] + red[2] + red[3] + bf[0];
}

// ================================ launch ======================================
extern "C" void kernel_launch(void* const* d_in, const int* in_sizes, int n_in,
                              void* d_out, int out_size) {
    const float* x     = (const float*)d_in[0];
    const int*   ind   = (const int*)  d_in[1];
    const float* ln_g  = (const float*)d_in[2];
    const float* ln_b  = (const float*)d_in[3];
    const float* W_ih0 = (const float*)d_in[4];
    const float* W_hh0 = (const float*)d_in[5];
    const float* b_ih0 = (const float*)d_in[6];
    const float* b_hh0 = (const float*)d_in[7];
    const float* W_ih1 = (const float*)d_in[8];
    const float* W_hh1 = (const float*)d_in[9];
    const float* b_ih1 = (const float*)d_in[10];
    const float* b_hh1 = (const float*)d_in[11];
    const float* Wp    = (const float*)d_in[12];
    const float* bp    = (const float*)d_in[13];
    const float* proto = (const float*)d_in[14];
    const float* Ws    = (const float*)d_in[15];
    const float* bs    = (const float*)d_in[16];
    const float* Wa    = (const float*)d_in[17];
    const float* ba    = (const float*)d_in[18];
    const float* Wf    = (const float*)d_in[19];
    const float* bf    = (const float*)d_in[20];
    float* out = (float*)d_out;

    cudaFuncSetAttribute(gemm128,      cudaFuncAttributeMaxDynamicSharedMemorySize, (int)GEMM_SMEM);
    cudaFuncSetAttribute(gemm_mma,     cudaFuncAttributeMaxDynamicSharedMemorySize, (int)MMA_SMEM);
    cudaFuncSetAttribute(gru_scan_mma, cudaFuncAttributeMaxDynamicSharedMemorySize, (int)SCAN2_SMEM);

    float *xg, *h1, *es, *t1, *ep, *er, *eh, *eres, *ea, *beta, *m1, *m2;
    float *m1p, *m2p, *idn, *ide, *isdn, *ide2;
    cudaGetSymbolAddress((void**)&xg,  g_xg);
    cudaGetSymbolAddress((void**)&h1,  g_h1);
    cudaGetSymbolAddress((void**)&es,  g_es);
    cudaGetSymbolAddress((void**)&t1,  g_t1);
    cudaGetSymbolAddress((void**)&ep,  g_ep);
    cudaGetSymbolAddress((void**)&er,  g_er);
    cudaGetSymbolAddress((void**)&eh,  g_eh);
    cudaGetSymbolAddress((void**)&eres,g_eres);
    cudaGetSymbolAddress((void**)&ea,  g_ea);
    cudaGetSymbolAddress((void**)&beta,g_beta);
    cudaGetSymbolAddress((void**)&m1,  g_m1);
    cudaGetSymbolAddress((void**)&m2,  g_m2);
    cudaGetSymbolAddress((void**)&m1p, g_m1p);
    cudaGetSymbolAddress((void**)&m2p, g_m2p);
    cudaGetSymbolAddress((void**)&idn, g_idn);
    cudaGetSymbolAddress((void**)&ide, g_ide);
    cudaGetSymbolAddress((void**)&isdn,g_isdn);
    cudaGetSymbolAddress((void**)&ide2,g_ide2);

    const int MROWS = NN_ * TT_;   // 256000

    gemm_mma<<<MROWS / 128, 512, MMA_SMEM>>>(x, W_ih0, b_ih0, xg, 1, ln_g, ln_b);
    gru_scan_mma<<<NN_ / 32, 512, SCAN2_SMEM>>>(xg, W_hh0, b_hh0, h1, nullptr);
    gemm_mma<<<MROWS / 128, 512, MMA_SMEM>>>(h1, W_ih1, b_ih1, xg, 0, ln_g, ln_b);
    gru_scan_mma<<<NN_ / 32, 512, SCAN2_SMEM>>>(xg, W_hh1, b_hh1, nullptr, es);
    gemm128<<<dim3((NN_ + 127) / 128, 1), 256, GEMM_SMEM>>>(es, Wp, nullptr, t1, NN_, HH_, 0);
    degrees_kernel<<<EE_ + (NN_ + 255) / 256, 256>>>(ind, idn, ide);
    prior_m_part<<<dim3(EE_, NCH_), 128>>>(ind, t1, m1p);
    prior_m_fin<<<EE_, 128>>>(m1p, ide, m1);
    prior_beta_kernel<<<NN_, 128>>>(ind, m1, idn, bp, es, proto, ep, er, beta, isdn);
    de2_kernel<<<KK_, 256>>>(beta, ide2);
    gemm128<<<dim3((NN_ + 127) / 128, 1), 256, GEMM_SMEM>>>(er, Ws, bs, t1, NN_, HH_, 0);
    soft_m_part<<<dim3(KK_, NCH_), 128>>>(beta, t1, m2p);
    soft_m_fin<<<KK_, 128>>>(m2p, ide2, m2);
    soft_out_kernel<<<NN_, 128>>>(beta, m2, isdn, er, eh, eres);
    gemm128<<<dim3((NN_ + 127) / 128, 1), 256, GEMM_SMEM>>>(eres, Wa, ba, ea, NN_, HH_, 1);
    final_kernel<<<NN_, 128>>>(ep, eh, ea, Wf, bf, out);
}